// round 12
// baseline (speedup 1.0000x reference)
#include <cuda_runtime.h>

// x shape [3, 5, 32, 64, 32, 32] -> 30720 images of 32x32
#define N_IMGS   30720
#define N_OUT    480
#define PATCHES  64
#define HW       1024
#define WPB      8          // warps (=images) per block
#define MAXRUNS  512        // <= 16 runs/row * 32 rows

// Cross-block accumulation scratch; self-resetting each replay.
__device__ int g_sum[N_OUT];
__device__ int g_cnt[N_OUT];

// UF word: [31:16] parent id, [15:0] static run size. All merge-phase stores
// (hook or halve) preserve the low 16 bits. In the count phase, roots' low
// bits accumulate the component total via atomicAdd (<=1024, never carries).

__device__ __forceinline__ int ufind(unsigned* L, int a, unsigned& wroot) {
    while (true) {
        unsigned w = L[a];
        int p = (int)(w >> 16);
        if (p == a) { wroot = w; return a; }
        unsigned pw = L[p];
        int gp = (int)(pw >> 16);
        if (gp == p) { wroot = pw; return p; }
        L[a] = ((unsigned)gp << 16) | (w & 0xffffu);   // halve, keep low bits
        a = gp;
    }
}

// Merge two components; returns the surviving (min) root as a new find hint.
__device__ __forceinline__ int umerge(unsigned* L, int a, int b) {
    while (true) {
        unsigned wa, wb;
        a = ufind(L, a, wa);
        b = ufind(L, b, wb);
        if (a == b) return a;
        int mn, mx; unsigned wmx;
        if (a < b) { mn = a; mx = b; wmx = wb; }
        else       { mn = b; mx = a; wmx = wa; }
        unsigned old = atomicMin(&L[mx], ((unsigned)mn << 16) | (wmx & 0xffffu));
        if ((int)(old >> 16) == mx) return mn;   // linked root mx -> mn
        a = mn; b = (int)(old >> 16);            // lost race; merge survivors
    }
}

// Read-only find (count phase: roots' low bits are concurrently added to,
// but parent fields are stable and adds never carry into them).
__device__ __forceinline__ int ufind_ro(const unsigned* L, int a) {
    int p = (int)(L[a] >> 16);
    while (p != a) { a = p; p = (int)(L[a] >> 16); }
    return a;
}

// Isolate lowest maximal run of 1s (low = lowest set bit of rem).
__device__ __forceinline__ unsigned lowest_run(unsigned rem, unsigned low) {
    return rem & (rem ^ (rem + low));
}

// One warp per 32x32 image; lane = row.
__global__ void __launch_bounds__(32 * WPB, 8)
ccl_kernel(const float* __restrict__ x, float* __restrict__ out) {
    __shared__ unsigned UF[WPB][MAXRUNS];

    const int lane = threadIdx.x & 31;
    const int warp = threadIdx.x >> 5;
    const int img  = blockIdx.x * WPB + warp;

    // ---- Row bitmask, ballot-free: each lane reads its OWN 128B row ----
    // 8 independent LDG.128; 2 ops/element to set mask bits. No VOTE/SHFL.
    const float4* row4 = (const float4*)(x + (size_t)img * HW) + lane * 8;
    unsigned m = 0;
    #pragma unroll
    for (int j = 0; j < 8; j++) {
        float4 v = __ldcs(&row4[j]);
        if (v.x != 0.0f) m |= 1u << (4 * j + 0);
        if (v.y != 0.0f) m |= 1u << (4 * j + 1);
        if (v.z != 0.0f) m |= 1u << (4 * j + 2);
        if (v.w != 0.0f) m |= 1u << (4 * j + 3);
    }

    // ---- Run starts; per-row run-id base via warp scan ----
    const unsigned start = m & ~(m << 1);
    const int nmine = __popc(start);
    int scan = nmine;
    #pragma unroll
    for (int o = 1; o < 32; o <<= 1) {
        int v = __shfl_up_sync(0xFFFFFFFFu, scan, o);
        if (lane >= o) scan += v;
    }
    const int base  = scan - nmine;
    const int total = __shfl_sync(0xFFFFFFFFu, scan, 31);

    // ---- Init: each lane writes its runs' (parent=self | size) words ----
    unsigned* uf = UF[warp];
    {
        unsigned rem = m;
        int idx = base;
        while (rem) {
            unsigned low   = rem & (unsigned)(-(int)rem);
            unsigned rmask = lowest_run(rem, low);
            rem &= ~rmask;
            uf[idx] = ((unsigned)idx << 16) | (unsigned)__popc(rmask);
            idx++;
        }
    }
    __syncwarp();

    // ---- Merge inter-row edges: one edge per maximal segment of m & nextrow.
    //      Root-cache: consecutive segments often share parent run a.
    unsigned nm     = __shfl_down_sync(0xFFFFFFFFu, m, 1);
    unsigned nstart = __shfl_down_sync(0xFFFFFFFFu, start, 1);
    int      nbase  = __shfl_down_sync(0xFFFFFFFFu, base, 1);
    if (lane == 31) nm = 0;
    {
        unsigned ov   = m & nm;
        unsigned segs = ov & ~(ov << 1);
        int prev_a = -1, hint = -1;
        while (segs) {
            int j = __ffs(segs) - 1;
            segs &= segs - 1;
            unsigned below = (2u << j) - 1;            // bits 0..j (j=31 -> all)
            int a = base  + __popc(start  & below) - 1;
            int b = nbase + __popc(nstart & below) - 1;
            // Stale-but-in-component hint is a valid find start.
            hint = umerge(uf, (a == prev_a) ? hint : a, b);
            prev_a = a;
        }
    }
    __syncwarp();

    // ---- Fused count + max: non-roots add their static size into the root;
    //      the LAST adder to a root observes the component's final total.
    int v = 0;
    for (int i = lane; i < total; i += 32) {
        unsigned w  = uf[i];
        int r       = (int)(w >> 16);
        unsigned sz = w & 0xffffu;
        if (r == i) {
            v = max(v, (int)sz);                       // covers singleton roots
        } else {
            r = ufind_ro(uf, r);
            unsigned old = atomicAdd(&uf[r], sz);
            v = max(v, (int)((old + sz) & 0xffffu));   // last adder sees total
        }
    }

    // ---- Warp reductions via REDUX; background count competes for the max ----
    v = __reduce_max_sync(0xFFFFFFFFu, v);
    int bg = __reduce_add_sync(0xFFFFFFFFu, 32 - __popc(m));

    // ---- Fused reduction: 64th arriver per group finishes the output ----
    if (lane == 0) {
        const int my = max(v, bg);
        const int o = img >> 6;                        // img / PATCHES
        atomicAdd(&g_sum[o], my);
        __threadfence();
        int n = atomicAdd(&g_cnt[o], 1);
        if (n == PATCHES - 1) {
            __threadfence();
            int total_s = atomicExch(&g_sum[o], 0);    // read + reset for replay
            out[o] = (float)(total_s / PATCHES);       // truncating int divide
            atomicExch(&g_cnt[o], 0);                  // reset for replay
        }
    }
}

extern "C" void kernel_launch(void* const* d_in, const int* in_sizes, int n_in,
                              void* d_out, int out_size) {
    const float* x = (const float*)d_in[0];
    float* out = (float*)d_out;
    ccl_kernel<<<N_IMGS / WPB, 32 * WPB>>>(x, out);
}

// round 14
// speedup vs baseline: 1.9995x; 1.9995x over previous
#include <cuda_runtime.h>

// x shape [3, 5, 32, 64, 32, 32] -> 30720 images of 32x32
#define N_IMGS   30720
#define N_OUT    480
#define PATCHES  64
#define HW       1024
#define WPB      8          // warps (=images) per block
#define MAXRUNS  512        // <= 16 runs/row * 32 rows

// Cross-block accumulation scratch; self-resetting each replay.
__device__ int g_sum[N_OUT];
__device__ int g_cnt[N_OUT];

// UF word: [31:16] parent id, [15:0] static run size. All merge-phase stores
// (hook or halve) preserve the low 16 bits. In the count phase, roots' low
// bits accumulate the component total via atomicAdd (<=1024, never carries).

__device__ __forceinline__ int ufind(unsigned* L, int a, unsigned& wroot) {
    while (true) {
        unsigned w = L[a];
        int p = (int)(w >> 16);
        if (p == a) { wroot = w; return a; }
        unsigned pw = L[p];
        int gp = (int)(pw >> 16);
        if (gp == p) { wroot = pw; return p; }
        L[a] = ((unsigned)gp << 16) | (w & 0xffffu);   // halve, keep low bits
        a = gp;
    }
}

// Merge two components; returns the surviving (min) root as a new find hint.
__device__ __forceinline__ int umerge(unsigned* L, int a, int b) {
    while (true) {
        unsigned wa, wb;
        a = ufind(L, a, wa);
        b = ufind(L, b, wb);
        if (a == b) return a;
        int mn, mx; unsigned wmx;
        if (a < b) { mn = a; mx = b; wmx = wb; }
        else       { mn = b; mx = a; wmx = wa; }
        unsigned old = atomicMin(&L[mx], ((unsigned)mn << 16) | (wmx & 0xffffu));
        if ((int)(old >> 16) == mx) return mn;   // linked root mx -> mn
        a = mn; b = (int)(old >> 16);            // lost race; merge survivors
    }
}

// Read-only find (count phase: roots' low bits are concurrently added to,
// but parent fields are stable and adds never carry into them).
__device__ __forceinline__ int ufind_ro(const unsigned* L, int a) {
    int p = (int)(L[a] >> 16);
    while (p != a) { a = p; p = (int)(L[a] >> 16); }
    return a;
}

// Isolate lowest maximal run of 1s (low = lowest set bit of rem).
__device__ __forceinline__ unsigned lowest_run(unsigned rem, unsigned low) {
    return rem & (rem ^ (rem + low));
}

// Spread 8 bits so bit k lands at position 4k.
__device__ __forceinline__ unsigned spread4(unsigned x) {
    x = (x | (x << 12)) & 0x000F000Fu;
    x = (x | (x << 6))  & 0x03030303u;
    x = (x | (x << 3))  & 0x11111111u;
    return x;
}

// One warp per 32x32 image; lane = row.
__global__ void __launch_bounds__(32 * WPB, 8)
ccl_kernel(const float* __restrict__ x, float* __restrict__ out) {
    __shared__ unsigned UF[WPB][MAXRUNS];

    const int lane = threadIdx.x & 31;
    const int warp = threadIdx.x >> 5;
    const int img  = blockIdx.x * WPB + warp;

    // ---- Row bitmasks: 8 COALESCED float4 loads, 4 ballots each ----
    // (Coalesced per instruction: 1 L1 wavefront per LDG.128 — the per-lane-row
    //  variant cost 32 wavefronts/LDG and regressed 2x. Keep ballots.)
    const float4* p4 = (const float4*)(x + (size_t)img * HW);
    unsigned c0 = 0, c1 = 0, c2 = 0, c3 = 0;
    #pragma unroll
    for (int i = 0; i < 8; i++) {
        float4 v = __ldcs(&p4[i * 32 + lane]);
        unsigned b0 = __ballot_sync(0xFFFFFFFFu, v.x != 0.0f);
        unsigned b1 = __ballot_sync(0xFFFFFFFFu, v.y != 0.0f);
        unsigned b2 = __ballot_sync(0xFFFFFFFFu, v.z != 0.0f);
        unsigned b3 = __ballot_sync(0xFFFFFFFFu, v.w != 0.0f);
        if ((lane >> 2) == i) {
            int sh = (lane & 3) * 8;
            c0 = (b0 >> sh) & 0xffu;
            c1 = (b1 >> sh) & 0xffu;
            c2 = (b2 >> sh) & 0xffu;
            c3 = (b3 >> sh) & 0xffu;
        }
    }
    const unsigned m = spread4(c0) | (spread4(c1) << 1)
                     | (spread4(c2) << 2) | (spread4(c3) << 3);

    // ---- Run starts; per-row run-id base via warp scan ----
    const unsigned start = m & ~(m << 1);
    const int nmine = __popc(start);
    int scan = nmine;
    #pragma unroll
    for (int o = 1; o < 32; o <<= 1) {
        int v = __shfl_up_sync(0xFFFFFFFFu, scan, o);
        if (lane >= o) scan += v;
    }
    const int base  = scan - nmine;
    const int total = __shfl_sync(0xFFFFFFFFu, scan, 31);

    // ---- Init: each lane writes its runs' (parent=self | size) words ----
    unsigned* uf = UF[warp];
    {
        unsigned rem = m;
        int idx = base;
        while (rem) {
            unsigned low   = rem & (unsigned)(-(int)rem);
            unsigned rmask = lowest_run(rem, low);
            rem &= ~rmask;
            uf[idx] = ((unsigned)idx << 16) | (unsigned)__popc(rmask);
            idx++;
        }
    }
    __syncwarp();

    // ---- Merge inter-row edges: one edge per maximal segment of m & nextrow.
    //      Root-cache: consecutive segments often share parent run a.
    unsigned nm     = __shfl_down_sync(0xFFFFFFFFu, m, 1);
    unsigned nstart = __shfl_down_sync(0xFFFFFFFFu, start, 1);
    int      nbase  = __shfl_down_sync(0xFFFFFFFFu, base, 1);
    if (lane == 31) nm = 0;
    {
        unsigned ov   = m & nm;
        unsigned segs = ov & ~(ov << 1);
        int prev_a = -1, hint = -1;
        while (segs) {
            int j = __ffs(segs) - 1;
            segs &= segs - 1;
            unsigned below = (2u << j) - 1;            // bits 0..j (j=31 -> all)
            int a = base  + __popc(start  & below) - 1;
            int b = nbase + __popc(nstart & below) - 1;
            // Stale-but-in-component hint is a valid find start.
            hint = umerge(uf, (a == prev_a) ? hint : a, b);
            prev_a = a;
        }
    }
    __syncwarp();

    // ---- Fused count + max: non-roots add their static size into the root;
    //      the LAST adder to a root observes the component's final total.
    int v = 0;
    for (int i = lane; i < total; i += 32) {
        unsigned w  = uf[i];
        int r       = (int)(w >> 16);
        unsigned sz = w & 0xffffu;
        if (r == i) {
            v = max(v, (int)sz);                       // covers singleton roots
        } else {
            r = ufind_ro(uf, r);
            unsigned old = atomicAdd(&uf[r], sz);
            v = max(v, (int)((old + sz) & 0xffffu));   // last adder sees total
        }
    }

    // ---- Warp reductions via REDUX; background count competes for the max ----
    v = __reduce_max_sync(0xFFFFFFFFu, v);
    int bg = __reduce_add_sync(0xFFFFFFFFu, 32 - __popc(m));

    // ---- Fused reduction: 64th arriver per group finishes the output ----
    if (lane == 0) {
        const int my = max(v, bg);
        const int o = img >> 6;                        // img / PATCHES
        atomicAdd(&g_sum[o], my);
        __threadfence();
        int n = atomicAdd(&g_cnt[o], 1);
        if (n == PATCHES - 1) {
            __threadfence();
            int total_s = atomicExch(&g_sum[o], 0);    // read + reset for replay
            out[o] = (float)(total_s / PATCHES);       // truncating int divide
            atomicExch(&g_cnt[o], 0);                  // reset for replay
        }
    }
}

extern "C" void kernel_launch(void* const* d_in, const int* in_sizes, int n_in,
                              void* d_out, int out_size) {
    const float* x = (const float*)d_in[0];
    float* out = (float*)d_out;
    ccl_kernel<<<N_IMGS / WPB, 32 * WPB>>>(x, out);
}

// round 15
// speedup vs baseline: 2.2015x; 1.1010x over previous
#include <cuda_runtime.h>

// x shape [3, 5, 32, 64, 32, 32] -> 30720 images of 32x32
#define N_IMGS   30720
#define N_OUT    480
#define PATCHES  64
#define HW       1024
#define WPB      8          // warps (=images) per block
#define MAXRUNS  512        // <= 16 runs/row * 32 rows

// Cross-block accumulation scratch; self-resetting each replay.
__device__ int g_sum[N_OUT];
__device__ int g_cnt[N_OUT];

// UF entry (merge phase): plain parent id, upper bits zero.
// Count phase: upper 16 bits of each ROOT accumulate the component total via
// atomicAdd(sz<<16); parent id stays in the low bits (ids < 512, sums <= 1024).

__device__ __forceinline__ int ufind(int* P, int a) {
    while (true) {
        int p = P[a];
        if (p == a) return a;
        int gp = P[p];
        if (gp == p) return p;
        P[a] = gp;              // path halving
        a = gp;
    }
}

// Merge; returns surviving (min) root as a find hint for the caller.
__device__ __forceinline__ int umerge(int* P, int a, int b) {
    while (true) {
        a = ufind(P, a);
        b = ufind(P, b);
        if (a == b) return a;
        int mn = min(a, b), mx = max(a, b);
        int old = atomicMin(&P[mx], mn);
        if (old == mx) return mn;   // linked root mx -> mn
        a = mn; b = old;            // lost race; merge survivors
    }
}

// Count-phase find: parent in low 16 bits (upper bits of roots hold counts).
__device__ __forceinline__ int ufind_cnt(const int* P, int a) {
    int p = P[a] & 0xffff;
    while (p != a) { a = p; p = P[a] & 0xffff; }
    return a;
}

// Isolate lowest maximal run of 1s (low = lowest set bit of rem).
__device__ __forceinline__ unsigned lowest_run(unsigned rem, unsigned low) {
    return rem & (rem ^ (rem + low));
}

// Spread 8 bits so bit k lands at position 4k.
__device__ __forceinline__ unsigned spread4(unsigned x) {
    x = (x | (x << 12)) & 0x000F000Fu;
    x = (x | (x << 6))  & 0x03030303u;
    x = (x | (x << 3))  & 0x11111111u;
    return x;
}

// One warp per 32x32 image; lane = row.
__global__ void __launch_bounds__(32 * WPB, 8)
ccl_kernel(const float* __restrict__ x, float* __restrict__ out) {
    __shared__ int UF[WPB][MAXRUNS];

    const int lane = threadIdx.x & 31;
    const int warp = threadIdx.x >> 5;
    const int img  = blockIdx.x * WPB + warp;

    // ---- Row bitmasks: 8 COALESCED float4 loads, 4 ballots each ----
    const float4* p4 = (const float4*)(x + (size_t)img * HW);
    unsigned c0 = 0, c1 = 0, c2 = 0, c3 = 0;
    #pragma unroll
    for (int i = 0; i < 8; i++) {
        float4 v = __ldcs(&p4[i * 32 + lane]);
        unsigned b0 = __ballot_sync(0xFFFFFFFFu, v.x != 0.0f);
        unsigned b1 = __ballot_sync(0xFFFFFFFFu, v.y != 0.0f);
        unsigned b2 = __ballot_sync(0xFFFFFFFFu, v.z != 0.0f);
        unsigned b3 = __ballot_sync(0xFFFFFFFFu, v.w != 0.0f);
        if ((lane >> 2) == i) {
            int sh = (lane & 3) * 8;
            c0 = (b0 >> sh) & 0xffu;
            c1 = (b1 >> sh) & 0xffu;
            c2 = (b2 >> sh) & 0xffu;
            c3 = (b3 >> sh) & 0xffu;
        }
    }
    const unsigned m = spread4(c0) | (spread4(c1) << 1)
                     | (spread4(c2) << 2) | (spread4(c3) << 3);

    // ---- Run starts; per-row run-id base via warp scan ----
    const unsigned start = m & ~(m << 1);
    const int nmine = __popc(start);
    int scan = nmine;
    #pragma unroll
    for (int o = 1; o < 32; o <<= 1) {
        int v = __shfl_up_sync(0xFFFFFFFFu, scan, o);
        if (lane >= o) scan += v;
    }
    const int base  = scan - nmine;
    const int total = __shfl_sync(0xFFFFFFFFu, scan, 31);

    // ---- Init: BALANCED loop, parent = self (sizes recomputed at count) ----
    int* uf = UF[warp];
    for (int i = lane; i < total; i += 32) uf[i] = i;
    __syncwarp();

    // ---- Merge inter-row edges: one edge per maximal segment of m & nextrow.
    //      Root-cache hint: consecutive segments often share parent run a.
    unsigned nm     = __shfl_down_sync(0xFFFFFFFFu, m, 1);
    unsigned nstart = __shfl_down_sync(0xFFFFFFFFu, start, 1);
    int      nbase  = __shfl_down_sync(0xFFFFFFFFu, base, 1);
    if (lane == 31) nm = 0;
    {
        unsigned ov   = m & nm;
        unsigned segs = ov & ~(ov << 1);
        int prev_a = -1, hint = -1;
        while (segs) {
            int j = __ffs(segs) - 1;
            segs &= segs - 1;
            unsigned below = (2u << j) - 1;            // bits 0..j (j=31 -> all)
            int a = base  + __popc(start  & below) - 1;
            int b = nbase + __popc(nstart & below) - 1;
            // Stale-but-in-component hint is a valid find start.
            hint = umerge(uf, (a == prev_a) ? hint : a, b);
            prev_a = a;
        }
    }
    __syncwarp();

    // ---- Count + max: each run adds its size into root's UPPER 16 bits;
    //      the LAST adder to a root observes the component's final total.
    //      (Earlier adders only underestimate — safe for max.) Branchless:
    //      roots are runs too and simply add like everyone else.
    int v = 0;
    {
        unsigned rem = m;
        int idx = base;
        while (rem) {
            unsigned low   = rem & (unsigned)(-(int)rem);
            unsigned rmask = lowest_run(rem, low);
            rem &= ~rmask;
            int sz = __popc(rmask);
            int r  = ufind_cnt(uf, idx);
            int old = atomicAdd(&uf[r], sz << 16);
            v = max(v, (old >> 16) + sz);              // last adder sees total
            idx++;
        }
    }

    // ---- Warp reductions via REDUX; background count competes for the max ----
    v = __reduce_max_sync(0xFFFFFFFFu, v);
    int bg = __reduce_add_sync(0xFFFFFFFFu, 32 - __popc(m));

    // ---- Fused reduction: 64th arriver per group finishes the output ----
    if (lane == 0) {
        const int my = max(v, bg);
        const int o = img >> 6;                        // img / PATCHES
        atomicAdd(&g_sum[o], my);
        __threadfence();
        int n = atomicAdd(&g_cnt[o], 1);
        if (n == PATCHES - 1) {
            __threadfence();
            int total_s = atomicExch(&g_sum[o], 0);    // read + reset for replay
            out[o] = (float)(total_s / PATCHES);       // truncating int divide
            atomicExch(&g_cnt[o], 0);                  // reset for replay
        }
    }
}

extern "C" void kernel_launch(void* const* d_in, const int* in_sizes, int n_in,
                              void* d_out, int out_size) {
    const float* x = (const float*)d_in[0];
    float* out = (float*)d_out;
    ccl_kernel<<<N_IMGS / WPB, 32 * WPB>>>(x, out);
}